// round 3
// baseline (speedup 1.0000x reference)
#include <cuda_runtime.h>

// KapoorConv: 2-layer GCN forward.
//   deg[i] = 1 + indegree(i);  dinv = rsqrt(deg)
//   L1: t1 = dinv .* (x @ W1);  acc1 = t1 + scatter_add(t1[src] -> dst)
//       h  = relu(dinv .* acc1)
//   L2: t2 = dinv .* (h @ W2);  acc2 = t2 + scatter_add(t2[src] -> dst)
//       out = dinv .* acc2 + b2
// (dinv factored: pre-scale rows once, scatter unweighted, post-scale.)

#define D 64
#define N_MAX 100000

// Scratch (device globals: no allocation allowed in kernel_launch)
__device__ __align__(16) float g_deg [N_MAX];
__device__ __align__(16) float g_dinv[N_MAX];
__device__ __align__(16) float g_t1  [N_MAX * D];
__device__ __align__(16) float g_acc1[N_MAX * D];
__device__ __align__(16) float g_t2  [N_MAX * D];

// ---------------- degree / dinv ----------------

__global__ void k_deg_init(int n) {
    int i = blockIdx.x * blockDim.x + threadIdx.x;
    if (i < n) g_deg[i] = 1.0f;   // self-loop
}

__global__ void k_deg_count(const int* __restrict__ dst, int E) {
    int i = blockIdx.x * blockDim.x + threadIdx.x;
    if (i < E) atomicAdd(&g_deg[dst[i]], 1.0f);
}

__global__ void k_dinv(int n) {
    int i = blockIdx.x * blockDim.x + threadIdx.x;
    if (i < n) g_dinv[i] = rsqrtf(g_deg[i]);
}

// ---------------- GEMM (warp per row, W in shared) ----------------
// out rows pre-scaled by dinv[row]; written to both outA (gather source)
// and outB (accumulator init == self-loop contribution).
// PRE: input row is acc1 of previous layer -> apply relu(dinv * v) on load.

template <bool PRE>
__device__ __forceinline__ void gemm_body(
    const float* __restrict__ X, const float* __restrict__ W,
    float* __restrict__ outA, float* __restrict__ outB, int n)
{
    __shared__ float Ws[D * D];
    for (int i = threadIdx.x; i < D * D; i += blockDim.x) Ws[i] = W[i];
    __syncthreads();

    int lane = threadIdx.x & 31;
    int row  = blockIdx.x * (blockDim.x >> 5) + (threadIdx.x >> 5);
    if (row >= n) return;

    float s  = g_dinv[row];
    float xa = X[row * D + lane];
    float xb = X[row * D + 32 + lane];
    if (PRE) {
        xa = fmaxf(xa * s, 0.0f);
        xb = fmaxf(xb * s, 0.0f);
    }

    float a0 = 0.0f, a1 = 0.0f;
    const float2* Ws2 = (const float2*)Ws;   // Ws2[k*32 + lane] = W[k][2*lane .. 2*lane+1]
#pragma unroll
    for (int k = 0; k < 32; ++k) {
        float xk = __shfl_sync(0xffffffffu, xa, k);
        float2 w = Ws2[k * 32 + lane];
        a0 = fmaf(xk, w.x, a0);
        a1 = fmaf(xk, w.y, a1);
    }
#pragma unroll
    for (int k = 0; k < 32; ++k) {
        float xk = __shfl_sync(0xffffffffu, xb, k);
        float2 w = Ws2[(k + 32) * 32 + lane];
        a0 = fmaf(xk, w.x, a0);
        a1 = fmaf(xk, w.y, a1);
    }

    float2 r;
    r.x = s * a0;
    r.y = s * a1;
    ((float2*)outA)[row * 32 + lane] = r;
    ((float2*)outB)[row * 32 + lane] = r;
}

__global__ void k_gemm1(const float* __restrict__ X, const float* __restrict__ W, int n) {
    gemm_body<false>(X, W, g_t1, g_acc1, n);
}

__global__ void k_gemm2(const float* __restrict__ W, float* __restrict__ out, int n) {
    gemm_body<true>(g_acc1, W, g_t2, out, n);
}

// ---------------- edge scatter: acc[dst] += T[src] ----------------
// 16 threads per edge, each handles one float4 of the 64-float row.
// Unweighted (dinv folded into rows). Vector red halves atomic op count 4x.

__device__ __forceinline__ void scatter_body(
    const int* __restrict__ src, const int* __restrict__ dst,
    const float4* __restrict__ T, float4* __restrict__ A, int E)
{
    long long t = (long long)blockIdx.x * blockDim.x + threadIdx.x;
    int e = (int)(t >> 4);
    if (e >= E) return;
    int c = (int)(t & 15);
    int si = __ldg(&src[e]);
    int di = __ldg(&dst[e]);
    float4 v = __ldg(&T[(long long)si * 16 + c]);
    float4* p = A + ((long long)di * 16 + c);
    asm volatile("red.global.add.v4.f32 [%0], {%1,%2,%3,%4};"
                 :: "l"(p), "f"(v.x), "f"(v.y), "f"(v.z), "f"(v.w)
                 : "memory");
}

__global__ void k_scatter1(const int* __restrict__ src, const int* __restrict__ dst, int E) {
    scatter_body(src, dst, (const float4*)g_t1, (float4*)g_acc1, E);
}

__global__ void k_scatter2(const int* __restrict__ src, const int* __restrict__ dst,
                           float* __restrict__ out, int E) {
    scatter_body(src, dst, (const float4*)g_t2, (float4*)out, E);
}

// ---------------- finalize: out = dinv .* out + b2 ----------------

__global__ void k_final(float* __restrict__ out, const float* __restrict__ b2, int n) {
    int i = blockIdx.x * blockDim.x + threadIdx.x;
    if (i >= n * D) return;
    int row = i >> 6;
    int c   = i & 63;
    out[i] = g_dinv[row] * out[i] + b2[c];
}

// ---------------- launch ----------------

extern "C" void kernel_launch(void* const* d_in, const int* in_sizes, int n_in,
                              void* d_out, int out_size)
{
    const float* x  = (const float*)d_in[0];   // [N, 64]
    const float* W1 = (const float*)d_in[1];   // [64, 64]
    const float* W2 = (const float*)d_in[2];   // [64, 64]
    const float* b2 = (const float*)d_in[3];   // [64]
    const int*   ei = (const int*)  d_in[4];   // [2, E]

    int n = in_sizes[0] / D;
    int E = in_sizes[4] / 2;
    const int* src = ei;
    const int* dst = ei + E;
    float* out = (float*)d_out;

    const int T = 256;
    int bN    = (n + T - 1) / T;
    int bE    = (E + T - 1) / T;
    int bRows = (n + (T / 32) - 1) / (T / 32);          // warp per row
    long long sthreads = (long long)E * 16;
    int bScat = (int)((sthreads + T - 1) / T);
    int bElem = (n * D + T - 1) / T;

    k_deg_init <<<bN,    T>>>(n);
    k_deg_count<<<bE,    T>>>(dst, E);
    k_dinv     <<<bN,    T>>>(n);

    k_gemm1    <<<bRows, T>>>(x, W1, n);
    k_scatter1 <<<bScat, T>>>(src, dst, E);

    k_gemm2    <<<bRows, T>>>(W2, out, n);
    k_scatter2 <<<bScat, T>>>(src, dst, out, E);

    k_final    <<<bElem, T>>>(out, b2, n);
}